// round 15
// baseline (speedup 1.0000x reference)
#include <cuda_runtime.h>
#include <math.h>

#define N_PIX      65536
#define NPTS       320
#define MIN_D      2.0f
#define DSTEP      (4.0f / 319.0f)
#define DENSITY    0.1f
#define CUT        2e-4f
#define INV_LN109  9.491221f               // 1 / ln(1/0.9)
#define RAYS_PER_BLOCK 32
#define NSEG       8
#define NBLK       (N_PIX / RAYS_PER_BLOCK)   // 2048
#define L2_09      (-0.15200309344504997f)    // log2(0.9)

// Scratch (device globals: no allocation allowed)
__device__ float  g_rgb[N_PIX];
__device__ double g_psum[NBLK];
__device__ double g_psumsq[NBLK];
__device__ float  g_pmin[NBLK];
__device__ float  g_pmax[NBLK];
__device__ float  g_norm[4];

// per-axis validity coverage: sum of valid-corner weights, factorized form
__device__ __forceinline__ float coverage(float v) {
    return fmaxf(0.0f, fminf(1.0f, fminf(v + 1.0f, 256.0f - v)));
}

__device__ __forceinline__ float sigma_at(float ax, float bx, float ay, float by,
                                          float az, float bz, int p) {
    const float pf = (float)p;
    const float ix = fmaf(ax, pf, bx);
    const float iy = fmaf(ay, pf, by);
    const float iz = fmaf(az, pf, bz);
    return DENSITY * coverage(ix) * coverage(iy) * coverage(iz);
}

// solve for real-p interval where a*p + b is in (vlo, vhi)
__device__ __forceinline__ void axis_win(float a, float b, float vlo, float vhi,
                                         float& lo, float& hi) {
    if (fabsf(a) < 1e-9f) {
        if (b > vlo && b < vhi) { lo = -1e30f; hi = 1e30f; }
        else                    { lo =  1e30f; hi = -1e30f; }
    } else {
        const float inv = 1.0f / a;
        const float p1 = (vlo - b) * inv;
        const float p2 = (vhi - b) * inv;
        lo = fminf(p1, p2); hi = fmaxf(p1, p2);
    }
}

// interior trilinear fetch (float-exact index arithmetic, one F2I)
__device__ __forceinline__ float tri_interior(const float* __restrict__ vol,
                                              float ix, float iy, float iz) {
    const float x0f = floorf(ix), y0f = floorf(iy), z0f = floorf(iz);
    const float fx = ix - x0f, fy = iy - y0f, fz = iz - z0f;
    const float idxf = fmaf(z0f, 65536.0f, fmaf(y0f, 256.0f, x0f)); // exact (< 2^24)
    const float* base = vol + (int)idxf;
    const float v000 = base[0];
    const float v001 = base[1];
    const float v010 = base[256];
    const float v011 = base[257];
    const float v100 = base[65536];
    const float v101 = base[65537];
    const float v110 = base[65536 + 256];
    const float v111 = base[65536 + 257];
    const float c00 = fmaf(fx, v001 - v000, v000);
    const float c01 = fmaf(fx, v011 - v010, v010);
    const float c10 = fmaf(fx, v101 - v100, v100);
    const float c11 = fmaf(fx, v111 - v110, v110);
    const float c0  = fmaf(fy, c01 - c00, c00);
    const float c1  = fmaf(fy, c11 - c10, c10);
    return fmaf(fz, c1 - c0, c0);
}

// boundary (fringe) sample: arithmetic sigma, per-corner-validity feat
__device__ __forceinline__ void fringe_sample(const float* __restrict__ vol,
                                              float ax, float bx, float ay, float by,
                                              float az, float bz, int p,
                                              float& T, float& rgb) {
    const float pf = (float)p;
    const float ix = fmaf(ax, pf, bx);
    const float iy = fmaf(ay, pf, by);
    const float iz = fmaf(az, pf, bz);
    const float sigma = DENSITY * coverage(ix) * coverage(iy) * coverage(iz);
    if (sigma > 0.0f) {
        const float x0f = floorf(ix), y0f = floorf(iy), z0f = floorf(iz);
        const float fx = ix - x0f, fy = iy - y0f, fz = iz - z0f;
        const int x0 = (int)x0f, y0 = (int)y0f, z0 = (int)z0f;
        const float wx[2] = {1.0f - fx, fx};
        const float wy[2] = {1.0f - fy, fy};
        const float wz[2] = {1.0f - fz, fz};
        float feat = 0.0f;
        #pragma unroll
        for (int zi = 0; zi < 2; ++zi) {
            const int Z = z0 + zi;
            if (Z < 0 || Z > 255) continue;
            #pragma unroll
            for (int yi = 0; yi < 2; ++yi) {
                const int Y = y0 + yi;
                if (Y < 0 || Y > 255) continue;
                #pragma unroll
                for (int xi = 0; xi < 2; ++xi) {
                    const int X = x0 + xi;
                    if (X < 0 || X > 255) continue;
                    feat = fmaf(wz[zi] * wy[yi] * wx[xi],
                                vol[(((Z << 8) + Y) << 8) + X], feat);
                }
            }
        }
        rgb = fmaf(sigma * T, feat, rgb);
        T *= (1.0f - sigma);
    }
}

__global__ __launch_bounds__(256, 5)   // 51 regs/thread: probe the occupancy midpoint
void render_kernel(const float* __restrict__ vol,
                   const float* __restrict__ Rm,
                   const float* __restrict__ Tv)
{
    const int t   = threadIdx.x;
    const int seg = t >> 5;          // 0..7 : depth eighth
    const int r   = t & 31;          // ray within block
    const int ray = blockIdx.x * RAYS_PER_BLOCK + r;
    const int w = ray & 255;         // image x (fast -> voxel-x contiguity)
    const int h = ray >> 8;

    const float xg = -1.0f + (float)w * (2.0f / 255.0f);
    const float yg = -1.0f + (float)h * (2.0f / 255.0f);

    const float r00 = Rm[0], r01 = Rm[1], r02 = Rm[2];
    const float r10 = Rm[3], r11 = Rm[4], r12 = Rm[5];
    const float r20 = Rm[6], r21 = Rm[7], r22 = Rm[8];
    const float Tx = Tv[0], Ty = Tv[1], Tz = Tv[2];

    const float half     = (3.0f / 256.0f) * 255.0f * 0.5f;
    const float inv_half = 1.0f / half;

    const float axl = (r00 * xg * 0.5f + r01 * yg * 0.5f + r02) * inv_half;
    const float ayl = (r10 * xg * 0.5f + r11 * yg * 0.5f + r12) * inv_half;
    const float azl = (r20 * xg * 0.5f + r21 * yg * 0.5f + r22) * inv_half;
    const float bxl = -(r00 * Tx + r01 * Ty + r02 * Tz) * inv_half;
    const float byl = -(r10 * Tx + r11 * Ty + r12 * Tz) * inv_half;
    const float bzl = -(r20 * Tx + r21 * Ty + r22 * Tz) * inv_half;

    // index coords as affine in SAMPLE INDEX p:  ii(p) = a*p + b
    const float Ax = 127.5f * axl, Bx = 127.5f * (bxl + 1.0f);
    const float Ay = 127.5f * ayl, By = 127.5f * (byl + 1.0f);
    const float Az = 127.5f * azl, Bz = 127.5f * (bzl + 1.0f);
    const float ax = Ax * DSTEP, bx = fmaf(Ax, MIN_D, Bx);
    const float ay = Ay * DSTEP, by = fmaf(Ay, MIN_D, By);
    const float az = Az * DSTEP, bz = fmaf(Az, MIN_D, Bz);

    // ---- analytic windows ----
    float lx, hx, ly, hy, lz, hz;
    axis_win(ax, bx, -1.0f, 256.0f, lx, hx);
    axis_win(ay, by, -1.0f, 256.0f, ly, hy);
    axis_win(az, bz, -1.0f, 256.0f, lz, hz);
    const float PLf = fmaxf(fmaxf(lx, ly), lz);
    const float PHf = fminf(fminf(hx, hy), hz);
    int PL = max(0,    (int)floorf(fmaxf(fminf(PLf, 1e9f), -1e9f)));
    int PH = min(NPTS, (int)ceilf (fmaxf(fminf(PHf, 1e9f), -1e9f)) + 1);
    if (PH < PL) PH = PL;

    // conservative strictly-interior window (all 8 corners valid)
    axis_win(ax, bx, 0.001f, 254.999f, lx, hx);
    axis_win(ay, by, 0.001f, 254.999f, ly, hy);
    axis_win(az, bz, 0.001f, 254.999f, lz, hz);
    const float QLf = fmaxf(fmaxf(lx, ly), lz);
    const float QHf = fminf(fminf(hx, hy), hz);
    int QL  = (int)floorf(fmaxf(fminf(QLf, 1e9f), -1e9f)) + 1;
    int QHe = (int)ceilf (fmaxf(fminf(QHf, 1e9f), -1e9f));
    QL  = max(QL, PL);
    QHe = min(QHe, PH);
    if (QHe < QL) { QL = PH; QHe = PH; }   // empty interior -> all fringe

    // ---- analytic effective ray end PE (first p with pre-sample T < CUT) ----
    int PE = PH;
    {
        float Tf = 1.0f;
        const int e1 = min(QL, PH);
        bool dead = false;
        for (int p = PL; p < e1; ++p) {
            Tf *= (1.0f - sigma_at(ax, bx, ay, by, az, bz, p));
            if (Tf < CUT) { dead = true; PE = p + 1; break; }
        }
        if (!dead) {
            const int n_int = QHe - QL;
            if (Tf < CUT) {
                PE = QL;
            } else if (n_int > 0) {
                const int mi = (int)(logf(Tf * (1.0f / CUT)) * INV_LN109);
                if (mi + 2 < n_int) PE = QL + mi + 2;  // +1 margin sample
            }
        }
        if (PE < PL) PE = PL;
    }

    // ---- this thread's depth chunk over the BALANCED range [PL, PE) ----
    const int span = PE - PL;
    const int L    = (span + NSEG - 1) / NSEG;
    int p0 = PL + seg * L;
    int p1 = min(p0 + L, PE);
    if (p0 > PE) p0 = PE;

    // ---- analytic start transmittance at p0 ----
    float T = 1.0f;
    {
        const int lim = p0;
        const int e1 = min(lim, QL);            // front fringe [PL, e1)
        for (int p = PL; p < e1; ++p)
            T *= (1.0f - sigma_at(ax, bx, ay, by, az, bz, p));
        const int m = min(lim, QHe) - QL;       // interior count before p0
        if (m > 0) T *= exp2f((float)m * L2_09);
        const int e2 = min(lim, PE);            // back fringe [QHe, e2)
        for (int p = QHe; p < e2; ++p)
            T *= (1.0f - sigma_at(ax, bx, ay, by, az, bz, p));
    }

    // ---- main loop: 3 phases over [p0, p1) ----
    float rgb = 0.0f;
    if (T >= CUT && p0 < p1) {
        // phase A: front fringe [p0, min(p1, QL))
        const int a1 = min(p1, QL);
        for (int p = p0; p < a1 && T >= CUT; ++p)
            fringe_sample(vol, ax, bx, ay, by, az, bz, p, T, rgb);

        // phase B: interior [max(p0,QL), min(p1,QHe)) : sigma = 0.1 exactly
        const int b0 = max(p0, QL), b1 = min(p1, QHe);
        if (b0 < b1) {
            int p = b0;
            // unroll x2: 16 corner loads in flight per iteration
            for (; p + 1 < b1; p += 2) {
                const float pf0 = (float)p;
                const float pf1 = (float)(p + 1);
                const float ix0 = fmaf(ax, pf0, bx);
                const float iy0 = fmaf(ay, pf0, by);
                const float iz0 = fmaf(az, pf0, bz);
                const float ix1 = fmaf(ax, pf1, bx);
                const float iy1 = fmaf(ay, pf1, by);
                const float iz1 = fmaf(az, pf1, bz);

                const float x0f0 = floorf(ix0), y0f0 = floorf(iy0), z0f0 = floorf(iz0);
                const float x0f1 = floorf(ix1), y0f1 = floorf(iy1), z0f1 = floorf(iz1);
                const float fx0 = ix0 - x0f0, fy0 = iy0 - y0f0, fz0 = iz0 - z0f0;
                const float fx1 = ix1 - x0f1, fy1 = iy1 - y0f1, fz1 = iz1 - z0f1;
                // exact float index arithmetic (values < 2^24)
                const float idxf0 = fmaf(z0f0, 65536.0f, fmaf(y0f0, 256.0f, x0f0));
                const float idxf1 = fmaf(z0f1, 65536.0f, fmaf(y0f1, 256.0f, x0f1));
                const float* b0p = vol + (int)idxf0;
                const float* b1p = vol + (int)idxf1;

                // issue all 16 loads before consuming
                const float a000 = b0p[0],            a001 = b0p[1];
                const float a010 = b0p[256],          a011 = b0p[257];
                const float a100 = b0p[65536],        a101 = b0p[65537];
                const float a110 = b0p[65536 + 256],  a111 = b0p[65536 + 257];
                const float q000 = b1p[0],            q001 = b1p[1];
                const float q010 = b1p[256],          q011 = b1p[257];
                const float q100 = b1p[65536],        q101 = b1p[65537];
                const float q110 = b1p[65536 + 256],  q111 = b1p[65536 + 257];

                const float ac00 = fmaf(fx0, a001 - a000, a000);
                const float ac01 = fmaf(fx0, a011 - a010, a010);
                const float ac10 = fmaf(fx0, a101 - a100, a100);
                const float ac11 = fmaf(fx0, a111 - a110, a110);
                const float ac0  = fmaf(fy0, ac01 - ac00, ac00);
                const float ac1  = fmaf(fy0, ac11 - ac10, ac10);
                const float feat0 = fmaf(fz0, ac1 - ac0, ac0);

                const float qc00 = fmaf(fx1, q001 - q000, q000);
                const float qc01 = fmaf(fx1, q011 - q010, q010);
                const float qc10 = fmaf(fx1, q101 - q100, q100);
                const float qc11 = fmaf(fx1, q111 - q110, q110);
                const float qc0  = fmaf(fy1, qc01 - qc00, qc00);
                const float qc1  = fmaf(fy1, qc11 - qc10, qc10);
                const float feat1 = fmaf(fz1, qc1 - qc0, qc0);

                rgb = fmaf(0.1f * T, feat0, rgb);
                rgb = fmaf(0.09f * T, feat1, rgb);
                T *= 0.81f;
            }
            if (p < b1) {
                const float pf = (float)p;
                const float feat = tri_interior(vol,
                                                fmaf(ax, pf, bx),
                                                fmaf(ay, pf, by),
                                                fmaf(az, pf, bz));
                rgb = fmaf(0.1f * T, feat, rgb);
                T *= 0.9f;
            }
        }

        // phase C: back fringe [max(p0,QHe), p1)
        const int c0 = max(p0, QHe);
        for (int p = c0; p < p1 && T >= CUT; ++p)
            fringe_sample(vol, ax, bx, ay, by, az, bz, p, T, rgb);
    }

    // ---- combine 8 depth-chunks per ray + warp-0 shuffle stats ----
    __shared__ float s_c[256];
    s_c[t] = rgb;
    __syncthreads();

    if (t < RAYS_PER_BLOCK) {   // warp 0 only
        const float myrgb =
            ((s_c[t]       + s_c[t + 32])  + (s_c[t + 64]  + s_c[t + 96])) +
            ((s_c[t + 128] + s_c[t + 160]) + (s_c[t + 192] + s_c[t + 224]));
        g_rgb[blockIdx.x * RAYS_PER_BLOCK + t] = myrgb;

        // warp-wide reduction: sum & sumsq in double, min, max (no smem, no bar)
        double sum = (double)myrgb;
        double ssq = sum * sum;
        float  mn  = myrgb;
        float  mx  = myrgb;
        #pragma unroll
        for (int o = 16; o > 0; o >>= 1) {
            sum += __shfl_down_sync(0xffffffffu, sum, o);
            ssq += __shfl_down_sync(0xffffffffu, ssq, o);
            mn = fminf(mn, __shfl_down_sync(0xffffffffu, mn, o));
            mx = fmaxf(mx, __shfl_down_sync(0xffffffffu, mx, o));
        }
        if (t == 0) {
            g_psum[blockIdx.x]   = sum;
            g_psumsq[blockIdx.x] = ssq;
            g_pmin[blockIdx.x]   = mn;
            g_pmax[blockIdx.x]   = mx;
        }
    }
}

__global__ __launch_bounds__(256)
void stats_kernel()
{
    __shared__ double s_sum[256];
    __shared__ double s_ssq[256];
    __shared__ float  s_min[256];
    __shared__ float  s_max[256];

    const int t = threadIdx.x;
    double sum = 0.0, ssq = 0.0;
    float  mn = 1e30f, mx = -1e30f;
    #pragma unroll
    for (int i = 0; i < NBLK / 256; ++i) {
        const int k = t + i * 256;
        sum += g_psum[k];
        ssq += g_psumsq[k];
        mn = fminf(mn, g_pmin[k]);
        mx = fmaxf(mx, g_pmax[k]);
    }
    s_sum[t] = sum; s_ssq[t] = ssq; s_min[t] = mn; s_max[t] = mx;
    __syncthreads();

    #pragma unroll
    for (int s = 128; s > 0; s >>= 1) {
        if (t < s) {
            s_sum[t] += s_sum[t + s];
            s_ssq[t] += s_ssq[t + s];
            s_min[t] = fminf(s_min[t], s_min[t + s]);
            s_max[t] = fmaxf(s_max[t], s_max[t + s]);
        }
        __syncthreads();
    }
    if (t == 0) {
        const double n    = (double)N_PIX;
        const double su   = s_sum[0];
        const double mean = su / n;
        double var = (s_ssq[0] - su * su / n) / (n - 1.0);
        if (var < 0.0) var = 0.0;
        const float stdv  = (float)sqrt(var);
        const float a     = 1.0f / (stdv + 1e-8f);
        const float sminv = (float)((double)s_min[0] - mean) * a;
        const float smaxv = (float)((double)s_max[0] - mean) * a;
        const float scale = 1.0f / (smaxv - sminv + 1e-8f);
        g_norm[0] = (float)mean;
        g_norm[1] = a;
        g_norm[2] = sminv;
        g_norm[3] = scale;
    }
}

// coalesced transpose + normalize: 32x32 smem tile (padded), 64 blocks
__global__ __launch_bounds__(256)
void normalize_kernel(float* __restrict__ out)
{
    __shared__ float tile[32][33];
    const int tx = threadIdx.x & 31;
    const int ty = threadIdx.x >> 5;       // 0..7
    const int bx = blockIdx.x & 7;         // i-tile
    const int by = blockIdx.x >> 3;        // j-tile

    // load rgb(j, i): j = by*32+row, i = bx*32+tx  (coalesced: i fastest)
    #pragma unroll
    for (int k = 0; k < 4; ++k) {
        const int row = ty + k * 8;
        tile[row][tx] = g_rgb[((by * 32 + row) << 8) + bx * 32 + tx];
    }
    __syncthreads();

    const float mean  = g_norm[0];
    const float a     = g_norm[1];
    const float sminv = g_norm[2];
    const float scale = g_norm[3];

    // write out(i, j) = f(rgb(j, i)): i = bx*32+row, j = by*32+tx (coalesced)
    #pragma unroll
    for (int k = 0; k < 4; ++k) {
        const int row = ty + k * 8;
        const float x = tile[tx][row];
        out[((bx * 32 + row) << 8) + by * 32 + tx] =
            ((x - mean) * a - sminv + 1e-8f) * scale;
    }
}

extern "C" void kernel_launch(void* const* d_in, const int* in_sizes, int n_in,
                              void* d_out, int out_size)
{
    const float* vol = (const float*)d_in[0]; // (1,1,256,256,256)
    const float* Rm  = (const float*)d_in[1]; // (1,3,3)
    const float* Tv  = (const float*)d_in[2]; // (1,3)
    float* out = (float*)d_out;               // (1,1,256,256)

    render_kernel<<<NBLK, 256>>>(vol, Rm, Tv);
    stats_kernel<<<1, 256>>>();
    normalize_kernel<<<64, 256>>>(out);
}

// round 16
// speedup vs baseline: 1.0696x; 1.0696x over previous
#include <cuda_runtime.h>
#include <math.h>

#define N_PIX      65536
#define NPTS       320
#define MIN_D      2.0f
#define DSTEP      (4.0f / 319.0f)
#define DENSITY    0.1f
#define CUT        2e-4f
#define INV_LN109  9.491221f               // 1 / ln(1/0.9)
#define RAYS_PER_BLOCK 32
#define NSEG       8
#define NBLK       (N_PIX / RAYS_PER_BLOCK)   // 2048
#define L2_09      (-0.15200309344504997f)    // log2(0.9)

// Scratch (device globals: no allocation allowed)
__device__ float  g_rgb[N_PIX];
__device__ double g_psum[NBLK];
__device__ double g_psumsq[NBLK];
__device__ float  g_pmin[NBLK];
__device__ float  g_pmax[NBLK];

// per-axis validity coverage: sum of valid-corner weights, factorized form
__device__ __forceinline__ float coverage(float v) {
    return fmaxf(0.0f, fminf(1.0f, fminf(v + 1.0f, 256.0f - v)));
}

__device__ __forceinline__ float sigma_at(float ax, float bx, float ay, float by,
                                          float az, float bz, int p) {
    const float pf = (float)p;
    const float ix = fmaf(ax, pf, bx);
    const float iy = fmaf(ay, pf, by);
    const float iz = fmaf(az, pf, bz);
    return DENSITY * coverage(ix) * coverage(iy) * coverage(iz);
}

// solve for real-p interval where a*p + b is in (vlo, vhi)
__device__ __forceinline__ void axis_win(float a, float b, float vlo, float vhi,
                                         float& lo, float& hi) {
    if (fabsf(a) < 1e-9f) {
        if (b > vlo && b < vhi) { lo = -1e30f; hi = 1e30f; }
        else                    { lo =  1e30f; hi = -1e30f; }
    } else {
        const float inv = 1.0f / a;
        const float p1 = (vlo - b) * inv;
        const float p2 = (vhi - b) * inv;
        lo = fminf(p1, p2); hi = fmaxf(p1, p2);
    }
}

// interior trilinear fetch (float-exact index arithmetic, one F2I)
__device__ __forceinline__ float tri_interior(const float* __restrict__ vol,
                                              float ix, float iy, float iz) {
    const float x0f = floorf(ix), y0f = floorf(iy), z0f = floorf(iz);
    const float fx = ix - x0f, fy = iy - y0f, fz = iz - z0f;
    const float idxf = fmaf(z0f, 65536.0f, fmaf(y0f, 256.0f, x0f)); // exact (< 2^24)
    const float* base = vol + (int)idxf;
    const float v000 = base[0];
    const float v001 = base[1];
    const float v010 = base[256];
    const float v011 = base[257];
    const float v100 = base[65536];
    const float v101 = base[65537];
    const float v110 = base[65536 + 256];
    const float v111 = base[65536 + 257];
    const float c00 = fmaf(fx, v001 - v000, v000);
    const float c01 = fmaf(fx, v011 - v010, v010);
    const float c10 = fmaf(fx, v101 - v100, v100);
    const float c11 = fmaf(fx, v111 - v110, v110);
    const float c0  = fmaf(fy, c01 - c00, c00);
    const float c1  = fmaf(fy, c11 - c10, c10);
    return fmaf(fz, c1 - c0, c0);
}

// boundary (fringe) sample: arithmetic sigma, per-corner-validity feat
__device__ __forceinline__ void fringe_sample(const float* __restrict__ vol,
                                              float ax, float bx, float ay, float by,
                                              float az, float bz, int p,
                                              float& T, float& rgb) {
    const float pf = (float)p;
    const float ix = fmaf(ax, pf, bx);
    const float iy = fmaf(ay, pf, by);
    const float iz = fmaf(az, pf, bz);
    const float sigma = DENSITY * coverage(ix) * coverage(iy) * coverage(iz);
    if (sigma > 0.0f) {
        const float x0f = floorf(ix), y0f = floorf(iy), z0f = floorf(iz);
        const float fx = ix - x0f, fy = iy - y0f, fz = iz - z0f;
        const int x0 = (int)x0f, y0 = (int)y0f, z0 = (int)z0f;
        const float wx[2] = {1.0f - fx, fx};
        const float wy[2] = {1.0f - fy, fy};
        const float wz[2] = {1.0f - fz, fz};
        float feat = 0.0f;
        #pragma unroll
        for (int zi = 0; zi < 2; ++zi) {
            const int Z = z0 + zi;
            if (Z < 0 || Z > 255) continue;
            #pragma unroll
            for (int yi = 0; yi < 2; ++yi) {
                const int Y = y0 + yi;
                if (Y < 0 || Y > 255) continue;
                #pragma unroll
                for (int xi = 0; xi < 2; ++xi) {
                    const int X = x0 + xi;
                    if (X < 0 || X > 255) continue;
                    feat = fmaf(wz[zi] * wy[yi] * wx[xi],
                                vol[(((Z << 8) + Y) << 8) + X], feat);
                }
            }
        }
        rgb = fmaf(sigma * T, feat, rgb);
        T *= (1.0f - sigma);
    }
}

__global__ __launch_bounds__(256, 5)   // 51 regs/thread (measured 48): best occ/MLP point
void render_kernel(const float* __restrict__ vol,
                   const float* __restrict__ Rm,
                   const float* __restrict__ Tv)
{
    const int t   = threadIdx.x;
    const int seg = t >> 5;          // 0..7 : depth eighth
    const int r   = t & 31;          // ray within block
    const int ray = blockIdx.x * RAYS_PER_BLOCK + r;
    const int w = ray & 255;         // image x (fast -> voxel-x contiguity)
    const int h = ray >> 8;

    const float xg = -1.0f + (float)w * (2.0f / 255.0f);
    const float yg = -1.0f + (float)h * (2.0f / 255.0f);

    const float r00 = Rm[0], r01 = Rm[1], r02 = Rm[2];
    const float r10 = Rm[3], r11 = Rm[4], r12 = Rm[5];
    const float r20 = Rm[6], r21 = Rm[7], r22 = Rm[8];
    const float Tx = Tv[0], Ty = Tv[1], Tz = Tv[2];

    const float half     = (3.0f / 256.0f) * 255.0f * 0.5f;
    const float inv_half = 1.0f / half;

    const float axl = (r00 * xg * 0.5f + r01 * yg * 0.5f + r02) * inv_half;
    const float ayl = (r10 * xg * 0.5f + r11 * yg * 0.5f + r12) * inv_half;
    const float azl = (r20 * xg * 0.5f + r21 * yg * 0.5f + r22) * inv_half;
    const float bxl = -(r00 * Tx + r01 * Ty + r02 * Tz) * inv_half;
    const float byl = -(r10 * Tx + r11 * Ty + r12 * Tz) * inv_half;
    const float bzl = -(r20 * Tx + r21 * Ty + r22 * Tz) * inv_half;

    // index coords as affine in SAMPLE INDEX p:  ii(p) = a*p + b
    const float Ax = 127.5f * axl, Bx = 127.5f * (bxl + 1.0f);
    const float Ay = 127.5f * ayl, By = 127.5f * (byl + 1.0f);
    const float Az = 127.5f * azl, Bz = 127.5f * (bzl + 1.0f);
    const float ax = Ax * DSTEP, bx = fmaf(Ax, MIN_D, Bx);
    const float ay = Ay * DSTEP, by = fmaf(Ay, MIN_D, By);
    const float az = Az * DSTEP, bz = fmaf(Az, MIN_D, Bz);

    // ---- analytic windows ----
    float lx, hx, ly, hy, lz, hz;
    axis_win(ax, bx, -1.0f, 256.0f, lx, hx);
    axis_win(ay, by, -1.0f, 256.0f, ly, hy);
    axis_win(az, bz, -1.0f, 256.0f, lz, hz);
    const float PLf = fmaxf(fmaxf(lx, ly), lz);
    const float PHf = fminf(fminf(hx, hy), hz);
    int PL = max(0,    (int)floorf(fmaxf(fminf(PLf, 1e9f), -1e9f)));
    int PH = min(NPTS, (int)ceilf (fmaxf(fminf(PHf, 1e9f), -1e9f)) + 1);
    if (PH < PL) PH = PL;

    // conservative strictly-interior window (all 8 corners valid)
    axis_win(ax, bx, 0.001f, 254.999f, lx, hx);
    axis_win(ay, by, 0.001f, 254.999f, ly, hy);
    axis_win(az, bz, 0.001f, 254.999f, lz, hz);
    const float QLf = fmaxf(fmaxf(lx, ly), lz);
    const float QHf = fminf(fminf(hx, hy), hz);
    int QL  = (int)floorf(fmaxf(fminf(QLf, 1e9f), -1e9f)) + 1;
    int QHe = (int)ceilf (fmaxf(fminf(QHf, 1e9f), -1e9f));
    QL  = max(QL, PL);
    QHe = min(QHe, PH);
    if (QHe < QL) { QL = PH; QHe = PH; }   // empty interior -> all fringe

    // ---- analytic effective ray end PE (first p with pre-sample T < CUT) ----
    int PE = PH;
    {
        float Tf = 1.0f;
        const int e1 = min(QL, PH);
        bool dead = false;
        for (int p = PL; p < e1; ++p) {
            Tf *= (1.0f - sigma_at(ax, bx, ay, by, az, bz, p));
            if (Tf < CUT) { dead = true; PE = p + 1; break; }
        }
        if (!dead) {
            const int n_int = QHe - QL;
            if (Tf < CUT) {
                PE = QL;
            } else if (n_int > 0) {
                const int mi = (int)(logf(Tf * (1.0f / CUT)) * INV_LN109);
                if (mi + 2 < n_int) PE = QL + mi + 2;  // +1 margin sample
            }
        }
        if (PE < PL) PE = PL;
    }

    // ---- this thread's depth chunk over the BALANCED range [PL, PE) ----
    const int span = PE - PL;
    const int L    = (span + NSEG - 1) / NSEG;
    int p0 = PL + seg * L;
    int p1 = min(p0 + L, PE);
    if (p0 > PE) p0 = PE;

    // ---- analytic start transmittance at p0 ----
    float T = 1.0f;
    {
        const int lim = p0;
        const int e1 = min(lim, QL);            // front fringe [PL, e1)
        for (int p = PL; p < e1; ++p)
            T *= (1.0f - sigma_at(ax, bx, ay, by, az, bz, p));
        const int m = min(lim, QHe) - QL;       // interior count before p0
        if (m > 0) T *= exp2f((float)m * L2_09);
        const int e2 = min(lim, PE);            // back fringe [QHe, e2)
        for (int p = QHe; p < e2; ++p)
            T *= (1.0f - sigma_at(ax, bx, ay, by, az, bz, p));
    }

    // ---- main loop: 3 phases over [p0, p1) ----
    float rgb = 0.0f;
    if (T >= CUT && p0 < p1) {
        // phase A: front fringe [p0, min(p1, QL))
        const int a1 = min(p1, QL);
        for (int p = p0; p < a1 && T >= CUT; ++p)
            fringe_sample(vol, ax, bx, ay, by, az, bz, p, T, rgb);

        // phase B: interior [max(p0,QL), min(p1,QHe)) : sigma = 0.1 exactly
        const int b0 = max(p0, QL), b1 = min(p1, QHe);
        if (b0 < b1) {
            int p = b0;
            // unroll x2: 16 corner loads in flight per iteration
            for (; p + 1 < b1; p += 2) {
                const float pf0 = (float)p;
                const float pf1 = (float)(p + 1);
                const float ix0 = fmaf(ax, pf0, bx);
                const float iy0 = fmaf(ay, pf0, by);
                const float iz0 = fmaf(az, pf0, bz);
                const float ix1 = fmaf(ax, pf1, bx);
                const float iy1 = fmaf(ay, pf1, by);
                const float iz1 = fmaf(az, pf1, bz);

                const float x0f0 = floorf(ix0), y0f0 = floorf(iy0), z0f0 = floorf(iz0);
                const float x0f1 = floorf(ix1), y0f1 = floorf(iy1), z0f1 = floorf(iz1);
                const float fx0 = ix0 - x0f0, fy0 = iy0 - y0f0, fz0 = iz0 - z0f0;
                const float fx1 = ix1 - x0f1, fy1 = iy1 - y0f1, fz1 = iz1 - z0f1;
                // exact float index arithmetic (values < 2^24)
                const float idxf0 = fmaf(z0f0, 65536.0f, fmaf(y0f0, 256.0f, x0f0));
                const float idxf1 = fmaf(z0f1, 65536.0f, fmaf(y0f1, 256.0f, x0f1));
                const float* b0p = vol + (int)idxf0;
                const float* b1p = vol + (int)idxf1;

                // issue all 16 loads before consuming
                const float a000 = b0p[0],            a001 = b0p[1];
                const float a010 = b0p[256],          a011 = b0p[257];
                const float a100 = b0p[65536],        a101 = b0p[65537];
                const float a110 = b0p[65536 + 256],  a111 = b0p[65536 + 257];
                const float q000 = b1p[0],            q001 = b1p[1];
                const float q010 = b1p[256],          q011 = b1p[257];
                const float q100 = b1p[65536],        q101 = b1p[65537];
                const float q110 = b1p[65536 + 256],  q111 = b1p[65536 + 257];

                const float ac00 = fmaf(fx0, a001 - a000, a000);
                const float ac01 = fmaf(fx0, a011 - a010, a010);
                const float ac10 = fmaf(fx0, a101 - a100, a100);
                const float ac11 = fmaf(fx0, a111 - a110, a110);
                const float ac0  = fmaf(fy0, ac01 - ac00, ac00);
                const float ac1  = fmaf(fy0, ac11 - ac10, ac10);
                const float feat0 = fmaf(fz0, ac1 - ac0, ac0);

                const float qc00 = fmaf(fx1, q001 - q000, q000);
                const float qc01 = fmaf(fx1, q011 - q010, q010);
                const float qc10 = fmaf(fx1, q101 - q100, q100);
                const float qc11 = fmaf(fx1, q111 - q110, q110);
                const float qc0  = fmaf(fy1, qc01 - qc00, qc00);
                const float qc1  = fmaf(fy1, qc11 - qc10, qc10);
                const float feat1 = fmaf(fz1, qc1 - qc0, qc0);

                rgb = fmaf(0.1f * T, feat0, rgb);
                rgb = fmaf(0.09f * T, feat1, rgb);
                T *= 0.81f;
            }
            if (p < b1) {
                const float pf = (float)p;
                const float feat = tri_interior(vol,
                                                fmaf(ax, pf, bx),
                                                fmaf(ay, pf, by),
                                                fmaf(az, pf, bz));
                rgb = fmaf(0.1f * T, feat, rgb);
                T *= 0.9f;
            }
        }

        // phase C: back fringe [max(p0,QHe), p1)
        const int c0 = max(p0, QHe);
        for (int p = c0; p < p1 && T >= CUT; ++p)
            fringe_sample(vol, ax, bx, ay, by, az, bz, p, T, rgb);
    }

    // ---- combine 8 depth-chunks per ray + warp-0 shuffle stats ----
    __shared__ float s_c[256];
    s_c[t] = rgb;
    __syncthreads();

    if (t < RAYS_PER_BLOCK) {   // warp 0 only
        const float myrgb =
            ((s_c[t]       + s_c[t + 32])  + (s_c[t + 64]  + s_c[t + 96])) +
            ((s_c[t + 128] + s_c[t + 160]) + (s_c[t + 192] + s_c[t + 224]));
        g_rgb[blockIdx.x * RAYS_PER_BLOCK + t] = myrgb;

        // warp-wide reduction: sum & sumsq in double, min, max (no smem, no bar)
        double sum = (double)myrgb;
        double ssq = sum * sum;
        float  mn  = myrgb;
        float  mx  = myrgb;
        #pragma unroll
        for (int o = 16; o > 0; o >>= 1) {
            sum += __shfl_down_sync(0xffffffffu, sum, o);
            ssq += __shfl_down_sync(0xffffffffu, ssq, o);
            mn = fminf(mn, __shfl_down_sync(0xffffffffu, mn, o));
            mx = fmaxf(mx, __shfl_down_sync(0xffffffffu, mx, o));
        }
        if (t == 0) {
            g_psum[blockIdx.x]   = sum;
            g_psumsq[blockIdx.x] = ssq;
            g_pmin[blockIdx.x]   = mn;
            g_pmax[blockIdx.x]   = mx;
        }
    }
}

// fused stats + coalesced transpose + normalize.
// Every block redundantly computes the SAME global stats from the 2048 partials
// (fixed order -> deterministic & identical across blocks), then normalizes its
// own 32x32 tile. Removes the single-block stats kernel + one launch gap.
__global__ __launch_bounds__(256)
void normalize_kernel(float* __restrict__ out)
{
    __shared__ float  tile[32][33];
    __shared__ double w_sum[8], w_ssq[8];
    __shared__ float  w_min[8], w_max[8];
    __shared__ float  s_norm[4];

    const int t  = threadIdx.x;
    const int tx = t & 31;
    const int ty = t >> 5;                 // warp id 0..7
    const int bx = blockIdx.x & 7;         // i-tile
    const int by = blockIdx.x >> 3;        // j-tile

    // start tile loads early (independent of stats)
    #pragma unroll
    for (int k = 0; k < 4; ++k) {
        const int row = ty + k * 8;
        tile[row][tx] = g_rgb[((by * 32 + row) << 8) + bx * 32 + tx];
    }

    // ---- redundant global stats: each thread folds 8 partials ----
    double sum = 0.0, ssq = 0.0;
    float  mn = 1e30f, mx = -1e30f;
    #pragma unroll
    for (int i = 0; i < NBLK / 256; ++i) {
        const int k = t + i * 256;
        sum += g_psum[k];
        ssq += g_psumsq[k];
        mn = fminf(mn, g_pmin[k]);
        mx = fmaxf(mx, g_pmax[k]);
    }
    #pragma unroll
    for (int o = 16; o > 0; o >>= 1) {
        sum += __shfl_down_sync(0xffffffffu, sum, o);
        ssq += __shfl_down_sync(0xffffffffu, ssq, o);
        mn = fminf(mn, __shfl_down_sync(0xffffffffu, mn, o));
        mx = fmaxf(mx, __shfl_down_sync(0xffffffffu, mx, o));
    }
    if (tx == 0) { w_sum[ty] = sum; w_ssq[ty] = ssq; w_min[ty] = mn; w_max[ty] = mx; }
    __syncthreads();
    if (t == 0) {
        double S = 0.0, Q = 0.0;
        float  MN = 1e30f, MX = -1e30f;
        #pragma unroll
        for (int i = 0; i < 8; ++i) {
            S += w_sum[i]; Q += w_ssq[i];
            MN = fminf(MN, w_min[i]); MX = fmaxf(MX, w_max[i]);
        }
        const double n    = (double)N_PIX;
        const double mean = S / n;
        double var = (Q - S * S / n) / (n - 1.0);
        if (var < 0.0) var = 0.0;
        const float stdv  = (float)sqrt(var);
        const float a     = 1.0f / (stdv + 1e-8f);
        const float sminv = (float)((double)MN - mean) * a;
        const float smaxv = (float)((double)MX - mean) * a;
        s_norm[0] = (float)mean;
        s_norm[1] = a;
        s_norm[2] = sminv;
        s_norm[3] = 1.0f / (smaxv - sminv + 1e-8f);
    }
    __syncthreads();

    const float mean  = s_norm[0];
    const float a     = s_norm[1];
    const float sminv = s_norm[2];
    const float scale = s_norm[3];

    // write out(i, j) = f(rgb(j, i)): coalesced
    #pragma unroll
    for (int k = 0; k < 4; ++k) {
        const int row = ty + k * 8;
        const float x = tile[tx][row];
        out[((bx * 32 + row) << 8) + by * 32 + tx] =
            ((x - mean) * a - sminv + 1e-8f) * scale;
    }
}

extern "C" void kernel_launch(void* const* d_in, const int* in_sizes, int n_in,
                              void* d_out, int out_size)
{
    const float* vol = (const float*)d_in[0]; // (1,1,256,256,256)
    const float* Rm  = (const float*)d_in[1]; // (1,3,3)
    const float* Tv  = (const float*)d_in[2]; // (1,3)
    float* out = (float*)d_out;               // (1,1,256,256)

    render_kernel<<<NBLK, 256>>>(vol, Rm, Tv);
    normalize_kernel<<<64, 256>>>(out);
}